// round 15
// baseline (speedup 1.0000x reference)
#include <cuda_runtime.h>
#include <cuda_fp16.h>
#include <math.h>

#define BB 2
#define CC 64
#define NPTS 4096
#define MM 256
#define NS 32
#define R2 0.04f

// -------- scratch (device globals; no allocation allowed) --------
struct ZScratch {
    float  G[BB*CC*CC];
    float  sv[BB*CC];
    double stat[48];      // s1[8],ss1[8],s2[8],ss2[8],s3[8],ss3[8]
    int    bar;
    int    bar2;
    int    cnt[BB*NPTS];
};
__device__ ZScratch g_z;

__device__ int     g_idx[BB*NPTS*NS];
__device__ __half2 g_featsh[BB*NPTS*(MM/2)];  // (B, N, M/2) fp16 pairs
__device__ __half2 g_h2[BB*NPTS*(MM/2)];      // (B, N, M/2) fp16 pairs

#define G_S1  (g_z.stat)
#define G_SS1 (g_z.stat + 8)
#define G_S2  (g_z.stat + 16)
#define G_SS2 (g_z.stat + 24)
#define G_S3  (g_z.stat + 32)
#define G_SS3 (g_z.stat + 40)

__device__ __forceinline__ float gelu_f(float v) {
    return 0.5f * v * (1.0f + erff(v * 0.70710678118654752f));
}

// -------- K1: prep = gram+GN1stats (blocks 0-127) || ball query (blocks 128-383) ----
#define PREP_SMEM 50176
__global__ void __launch_bounds__(256, 4) k_prep(const float* __restrict__ x,
                                                 const float* __restrict__ pos,
                                                 const float* __restrict__ w1,
                                                 const float* __restrict__ b1) {
    extern __shared__ char smu[];
    int tid = threadIdx.x;
    int blk = blockIdx.x;
    int warp = tid >> 5, lane = tid & 31;

    if (blk >= 128) {
        // ======== ball query: 32 points, 8 warps x 4 rounds ========
        float* sx = (float*)smu;
        float* sy = sx + NPTS;
        float* sz = sy + NPTS;
        int*   widx = (int*)(smu + 49152);
        int idx = blk - 128;
        int b = idx >> 7, nbase = (idx & 127) * 32;
        const float* pb = pos + b * 3 * NPTS;
        for (int i = tid; i < NPTS; i += 256) {
            sx[i] = pb[i];
            sy[i] = pb[NPTS + i];
            sz[i] = pb[2*NPTS + i];
        }
        __syncthreads();

        int* wl = widx + warp * NS;
        for (int r = 0; r < 4; r++) {
            int n = nbase + warp*4 + r;
            float xn = sx[n], yn = sy[n], zn = sz[n];
            float sqn = xn*xn + yn*yn + zn*zn;
            int cnt = 0, firstm = -1;
            for (int base = 0; base < NPTS && cnt < NS; base += 32) {
                int mq = base + lane;
                float xm = sx[mq], ym = sy[mq], zm = sz[mq];
                float sqm = xm*xm + ym*ym + zm*zm;
                float dot = xn*xm + yn*ym + zn*zm;
                float d = sqn + sqm - 2.0f * dot;
                bool q = !(d > R2);
                unsigned mask = __ballot_sync(0xffffffffu, q);
                if (mask) {
                    if (firstm < 0) firstm = base + __ffs(mask) - 1;
                    int nq = __popc(mask);
                    int slots = NS - cnt;
                    if (q) {
                        int rank = __popc(mask & ((1u << lane) - 1u));
                        if (rank < slots) wl[cnt + rank] = mq;
                    }
                    cnt += (nq < slots) ? nq : slots;
                }
            }
            __syncwarp();
            if (lane >= cnt) wl[lane] = firstm;
            __syncwarp();
            int j = wl[lane];
            g_idx[(b*NPTS + n)*NS + lane] = j;
            atomicAdd(&g_z.cnt[b*NPTS + j], 1);
            __syncwarp();
        }
        return;
    }

    // ======== gram partial: 64-n chunk ========
    {
        float* sA = (float*)smu;          // [c][n] pitch 68
        int b = blk >> 6, n0 = (blk & 63) * 64;
        for (int e = tid; e < 4096; e += 256) {
            int c = e >> 6, nn = e & 63;
            sA[c*68 + nn] = x[(b*CC + c)*NPTS + n0 + nn];
        }
        __syncthreads();

        int tx = tid & 15, ty = tid >> 4;
        float acc[4][4] = {};
#pragma unroll 16
        for (int k = 0; k < 64; k++) {
            float a[4], h[4];
#pragma unroll
            for (int i = 0; i < 4; i++) a[i] = sA[(ty*4 + i)*68 + k];
#pragma unroll
            for (int j = 0; j < 4; j++) h[j] = sA[(tx*4 + j)*68 + k];
#pragma unroll
            for (int i = 0; i < 4; i++)
#pragma unroll
                for (int j = 0; j < 4; j++)
                    acc[i][j] = fmaf(a[i], h[j], acc[i][j]);
        }
        float* Gb = g_z.G + b*CC*CC;
#pragma unroll
        for (int i = 0; i < 4; i++)
#pragma unroll
            for (int j = 0; j < 4; j++)
                atomicAdd(&Gb[(ty*4 + i)*CC + tx*4 + j], acc[i][j]);
        if (tid < CC) {
            float s = 0.f;
#pragma unroll
            for (int nn = 0; nn < 64; nn++) s += sA[tid*68 + nn];
            atomicAdd(&g_z.sv[b*CC + tid], s);
        }
    }

    __syncthreads();
    __threadfence();
    if (tid == 0) atomicAdd(&g_z.bar, 1);
    if (blk >= 8) return;

    if (tid == 0) {
        while (atomicAdd(&g_z.bar, 0) < 128) __nanosleep(128);
    }
    __syncthreads();

    // ======== GN1 stats (blocks 0-7) ========
    {
        float* sG  = (float*)smu;
        float* sw  = (float*)(smu + 16384);
        float* ssv = (float*)(smu + 33024);
        double* sd  = (double*)(smu + 33280);
        double* ssd = (double*)(smu + 33792);
        int bg = blk;
        int sb = bg >> 2, m0 = (bg & 3) * 64;
        for (int e = tid; e < CC*CC; e += 256) sG[e] = __ldcg(&g_z.G[sb*CC*CC + e]);
        for (int e = tid; e < 64*CC; e += 256) sw[(e >> 6)*65 + (e & 63)] = w1[(m0 + (e >> 6))*CC + (e & 63)];
        if (tid < CC) ssv[tid] = __ldcg(&g_z.sv[sb*CC + tid]);
        __syncthreads();

        int mi = tid >> 2, part = tid & 3;
        float q = 0.f, l = 0.f;
        const float* wrow = sw + mi*65;
#pragma unroll
        for (int cc = 0; cc < 16; cc++) {
            int c = part*16 + cc;
            float wc = wrow[c];
            float in0 = 0.f, in1 = 0.f;
#pragma unroll
            for (int c2 = 0; c2 < 64; c2 += 2) {
                in0 = fmaf(wrow[c2],   sG[c*CC + c2],   in0);
                in1 = fmaf(wrow[c2+1], sG[c*CC + c2+1], in1);
            }
            q = fmaf(wc, in0 + in1, q);
            l = fmaf(wc, ssv[c], l);
        }
        q += __shfl_down_sync(0xffffffffu, q, 1);
        q += __shfl_down_sync(0xffffffffu, q, 2);
        l += __shfl_down_sync(0xffffffffu, l, 1);
        l += __shfl_down_sync(0xffffffffu, l, 2);
        if (part == 0) {
            double bb = (double)b1[m0 + mi];
            sd[mi]  = (double)l + 4096.0 * bb;
            ssd[mi] = (double)q + 2.0 * bb * (double)l + 4096.0 * bb * bb;
        }
        __syncthreads();
        for (int s = 32; s > 0; s >>= 1) {
            if (tid < s) { sd[tid] += sd[tid + s]; ssd[tid] += ssd[tid + s]; }
            __syncthreads();
        }
        if (tid == 0) { G_S1[bg] = sd[0]; G_SS1[bg] = ssd[0]; }
    }
}

// -------- K2: GEMM1 (64m x 64n tile, 8m x 4n thread, 128 threads) + GN1 + GELU
//          + fp16 feats + count-weighted GN2 stats --------
__global__ void k_gemm1f(const float* __restrict__ x, const float* __restrict__ w1,
                         const float* __restrict__ b1, const float* __restrict__ g1,
                         const float* __restrict__ be1, const float* __restrict__ wd) {
    __shared__ float sWt[64*68];
    __shared__ float sX[64*64];
    __shared__ float red1[128], red2[128];
    int b = blockIdx.z, m0 = blockIdx.y * 64, n0 = blockIdx.x * 64;
    int tid = threadIdx.x;
    int bg = b*4 + blockIdx.y;

    for (int e = tid; e < 4096; e += 128) {
        int m = e >> 6, c = e & 63;
        sWt[c*68 + m] = w1[(m0 + m)*CC + c];
    }
    for (int e = tid; e < 4096; e += 128) {
        int c = e >> 6, nn = e & 63;
        sX[c*64 + nn] = x[(b*CC + c)*NPTS + n0 + nn];
    }
    __syncthreads();

    int tx = tid & 15, ty = tid >> 4;
    float acc[8][4] = {};
#pragma unroll 8
    for (int k = 0; k < 64; k++) {
        float4 a0 = *(float4*)&sWt[k*68 + ty*8];
        float4 a1 = *(float4*)&sWt[k*68 + ty*8 + 4];
        float4 h4 = *(float4*)&sX[k*64 + tx*4];
        float a[8] = {a0.x, a0.y, a0.z, a0.w, a1.x, a1.y, a1.z, a1.w};
        float h[4] = {h4.x, h4.y, h4.z, h4.w};
#pragma unroll
        for (int i = 0; i < 8; i++)
#pragma unroll
            for (int j = 0; j < 4; j++)
                acc[i][j] = fmaf(a[i], h[j], acc[i][j]);
    }

    double mean = __ldcg(&G_S1[bg]) * (1.0 / (64.0 * 4096.0));
    double var  = __ldcg(&G_SS1[bg]) * (1.0 / (64.0 * 4096.0)) - mean * mean;
    float rs = (float)rsqrt(var + 1e-5);
    float mn = (float)mean;

    float ga[8], bo[8], wm[8];
#pragma unroll
    for (int i = 0; i < 8; i++) {
        int m = m0 + ty*8 + i;
        float bb = b1[m];
        ga[i] = g1[m] * rs;
        bo[i] = be1[m] - (mn - bb) * ga[i];
        wm[i] = wd[m];
    }
    float w[4];
#pragma unroll
    for (int j = 0; j < 4; j++) w[j] = (float)__ldcg(&g_z.cnt[b*NPTS + n0 + tx*4 + j]);

    float lsum = 0.f, lss = 0.f;
#pragma unroll
    for (int j = 0; j < 4; j++) {
        __half2 hv[4];
#pragma unroll
        for (int p = 0; p < 4; p++) {
            float v0 = gelu_f(fmaf(acc[2*p][j],   ga[2*p],   bo[2*p]));
            float v1 = gelu_f(fmaf(acc[2*p+1][j], ga[2*p+1], bo[2*p+1]));
            hv[p] = __floats2half2_rn(v0, v1);
            float a0 = v0 * wm[2*p], a1 = v1 * wm[2*p+1];
            lsum = fmaf(w[j], a0 + a1, lsum);
            lss  = fmaf(w[j], a0*a0 + a1*a1, lss);
        }
        int n = n0 + tx*4 + j;
        __half2* dst = g_featsh + (size_t)(b*NPTS + n)*(MM/2) + (m0 >> 1) + ty*4;
        *(uint4*)dst = *(uint4*)hv;
    }

    red1[tid] = lsum; red2[tid] = lss;
    __syncthreads();
    for (int s = 64; s > 0; s >>= 1) {
        if (tid < s) { red1[tid] += red1[tid + s]; red2[tid] += red2[tid + s]; }
        __syncthreads();
    }
    if (tid == 0) {
        atomicAdd(&G_S2[bg],  (double)red1[0]);
        atomicAdd(&G_SS2[bg], (double)red2[0]);
    }
}

// -------- K3: gather (warp per point, uint4 loads) + GN2 + maxpool + GELU -> h2 fp16 --------
__global__ void k_gather(const float* __restrict__ wd, const float* __restrict__ gd,
                         const float* __restrict__ bed) {
    __shared__ float sA[MM], sBc[MM];
    __shared__ int sI[8*NS];
    int blk = blockIdx.x;
    int b = blk >> 9, n0 = (blk & 511) * 8;
    int tid = threadIdx.x;

    {
        int m = tid;
        int bg = b*4 + (m >> 6);
        double mean = G_S2[bg] * (1.0 / 8388608.0);
        double var  = G_SS2[bg] * (1.0 / 8388608.0) - mean * mean;
        float rsv = (float)rsqrt(var + 1e-5);
        sA[m]  = wd[m] * rsv * gd[m];
        sBc[m] = bed[m] - (float)((double)rsv * mean) * gd[m];
    }
    sI[tid] = g_idx[(b*NPTS + n0)*NS + tid];
    __syncthreads();

    int warp = tid >> 5, lane = tid & 31;
    int n = n0 + warp;
    const int* il = sI + warp * NS;
    const uint4* fb = ((const uint4*)(g_featsh + (size_t)b*NPTS*(MM/2))) + lane;

    __half2 hneg = __half2half2(__float2half(-65504.f));
    __half2 hpos = __half2half2(__float2half( 65504.f));
    __half2 mxA[4] = {hneg, hneg, hneg, hneg};
    __half2 mnA[4] = {hpos, hpos, hpos, hpos};
    __half2 mxB[4] = {hneg, hneg, hneg, hneg};
    __half2 mnB[4] = {hpos, hpos, hpos, hpos};

#pragma unroll
    for (int s = 0; s < NS; s += 2) {
        uint4 va = fb[(size_t)il[s]   * 32];
        uint4 vb = fb[(size_t)il[s+1] * 32];
        const __half2* ha = (const __half2*)&va;
        const __half2* hb = (const __half2*)&vb;
#pragma unroll
        for (int u = 0; u < 4; u++) {
            mxA[u] = __hmax2(mxA[u], ha[u]); mnA[u] = __hmin2(mnA[u], ha[u]);
            mxB[u] = __hmax2(mxB[u], hb[u]); mnB[u] = __hmin2(mnB[u], hb[u]);
        }
    }

    __half2 outv[4];
#pragma unroll
    for (int u = 0; u < 4; u++) {
        float2 fmx = __half22float2(__hmax2(mxA[u], mxB[u]));
        float2 fmn = __half22float2(__hmin2(mnA[u], mnB[u]));
        int ch = 8*lane + 2*u;
        float A0 = sA[ch],   B0 = sBc[ch];
        float A1 = sA[ch+1], B1 = sBc[ch+1];
        float v0 = (A0 >= 0.f) ? fmx.x : fmn.x;
        float v1 = (A1 >= 0.f) ? fmx.y : fmn.y;
        float r0 = gelu_f(fmaf(A0, v0, B0));
        float r1 = gelu_f(fmaf(A1, v1, B1));
        outv[u] = __floats2half2_rn(r0, r1);
    }
    ((uint4*)(g_h2 + (size_t)(b*NPTS + n)*(MM/2)))[lane] = *(uint4*)outv;
}

// -------- K4: GEMM2 single-stage split-K, fp16 operands, vector LDS.64 loads
//          (64c x 32n block, 2 k-groups, 4c x 4n thread)
//          + GN3 stats + barrier + apply + residual ----
// dyn smem 51200 B -> 4 CTAs/SM -> capacity 592 >= 256, barrier safe
#define G2_SMEM (256*64*2 + 256*36*2)
__global__ void __launch_bounds__(256, 4) k_gemm2f(
    const float* __restrict__ w2, const float* __restrict__ b2,
    const float* __restrict__ x,  const float* __restrict__ g2,
    const float* __restrict__ be2, float* __restrict__ out) {
    extern __shared__ char smc[];
    __half* sW2h = (__half*)smc;               // [k][64] halfs: 32768 B; reused as sRed
    __half* sHh  = (__half*)(smc + 32768);     // [k][36] halfs: 18432 B
    __shared__ float sacc[4], sss[4];
    __shared__ float sMean[4], sRs[4];

    int blk = blockIdx.x;
    int b = blk >> 7, n0 = (blk & 127) * 32;
    int tid = threadIdx.x;
    if (tid < 4) { sacc[tid] = 0.f; sss[tid] = 0.f; }

    // ---- stage w2 -> fp16 [k][c] pitch 64 (once) ----
    for (int e = tid; e < 4096; e += 256) {
        int c = e >> 6, kq = e & 63;
        float4 v = *(const float4*)&w2[c*MM + kq*4];
        sW2h[(4*kq + 0)*64 + c] = __float2half_rn(v.x);
        sW2h[(4*kq + 1)*64 + c] = __float2half_rn(v.y);
        sW2h[(4*kq + 2)*64 + c] = __float2half_rn(v.z);
        sW2h[(4*kq + 3)*64 + c] = __float2half_rn(v.w);
    }
    // ---- stage h2 -> fp16 [k][n] pitch 36 (once) ----
    for (int e = tid; e < 4096; e += 256) {
        int n = e >> 7, mp = e & 127;
        __half2 v = g_h2[(size_t)(b*NPTS + n0 + n)*(MM/2) + mp];
        sHh[(2*mp)*36 + n]     = __low2half(v);
        sHh[(2*mp + 1)*36 + n] = __high2half(v);
    }
    __syncthreads();

    int kg = tid >> 7;             // k-group 0..1 (128 k each)
    int t  = tid & 127;
    int cq = t >> 3, nq = t & 7;   // c-quad 0..15, n-quad 0..7

    float acc[4][4] = {};
    int k0 = kg * 128;
#pragma unroll 8
    for (int kk = 0; kk < 128; kk++) {
        int k = k0 + kk;
        uint2 wr = *(const uint2*)&sW2h[k*64 + cq*4];     // 4 w halfs (LDS.64)
        uint2 hr = *(const uint2*)&sHh[k*36 + nq*4];      // 4 h halfs (LDS.64)
        float2 a01 = __half22float2(*(const __half2*)&wr.x);
        float2 a23 = __half22float2(*(const __half2*)&wr.y);
        float2 h01 = __half22float2(*(const __half2*)&hr.x);
        float2 h23 = __half22float2(*(const __half2*)&hr.y);
        float a[4] = {a01.x, a01.y, a23.x, a23.y};
        float h[4] = {h01.x, h01.y, h23.x, h23.y};
#pragma unroll
        for (int i = 0; i < 4; i++)
#pragma unroll
            for (int j = 0; j < 4; j++)
                acc[i][j] = fmaf(a[i], h[j], acc[i][j]);
    }

    // reduce across the 2 k-groups via smem (sRed aliases dead sW2h: 16KB <= 32KB)
    __syncthreads();
    float* sRed = (float*)sW2h;
#pragma unroll
    for (int i = 0; i < 4; i++)
#pragma unroll
        for (int j = 0; j < 4; j++) {
            int p = (cq*4 + i)*32 + (nq*4 + j);    // c*32 + n
            sRed[kg*2048 + p] = acc[i][j];
        }
    __syncthreads();

    // thread handles p = tid + r*256, r=0..7 ; GN3 group of r is r>>1
    float val[8];
    float lsum[4] = {0.f,0.f,0.f,0.f}, lss[4] = {0.f,0.f,0.f,0.f};
#pragma unroll
    for (int r = 0; r < 8; r++) {
        int p = tid + r*256;
        float v = sRed[p] + sRed[2048 + p];
        int c = p >> 5;
        v += b2[c];
        val[r] = v;
        lsum[r >> 1] += v;
        lss[r >> 1]  += v*v;
    }
#pragma unroll
    for (int g = 0; g < 4; g++) {
#pragma unroll
        for (int o = 16; o > 0; o >>= 1) {
            lsum[g] += __shfl_down_sync(0xffffffffu, lsum[g], o);
            lss[g]  += __shfl_down_sync(0xffffffffu, lss[g],  o);
        }
    }
    if ((tid & 31) == 0) {
#pragma unroll
        for (int g = 0; g < 4; g++) {
            atomicAdd(&sacc[g], lsum[g]);
            atomicAdd(&sss[g],  lss[g]);
        }
    }
    __syncthreads();
    if (tid < 4) {
        atomicAdd(&G_S3[b*4 + tid],  (double)sacc[tid]);
        atomicAdd(&G_SS3[b*4 + tid], (double)sss[tid]);
        __threadfence();
    }
    __syncthreads();

    if (tid == 0) {
        atomicAdd(&g_z.bar2, 1);
        while (atomicAdd(&g_z.bar2, 0) < 256) __nanosleep(128);
    }
    __syncthreads();

    if (tid < 4) {
        double s  = atomicAdd(&G_S3[b*4 + tid],  0.0);
        double ss = atomicAdd(&G_SS3[b*4 + tid], 0.0);
        double mean = s * (1.0 / 65536.0);
        double var  = ss * (1.0 / 65536.0) - mean * mean;
        sMean[tid] = (float)mean;
        sRs[tid]   = (float)rsqrt(var + 1e-5);
    }
    __syncthreads();

#pragma unroll
    for (int r = 0; r < 8; r++) {
        int p = tid + r*256;
        int c = p >> 5, n = p & 31;
        int g = r >> 1;
        float ga = sRs[g] * g2[c];
        float bo = be2[c] - sMean[g] * ga;
        size_t off = (size_t)(b*CC + c)*NPTS + n0 + n;
        out[off] = fmaf(val[r], ga, bo) + x[off];
    }
}

extern "C" void kernel_launch(void* const* d_in, const int* in_sizes, int n_in,
                              void* d_out, int out_size) {
    const float* x   = (const float*)d_in[0];
    const float* pos = (const float*)d_in[1];
    const float* w1  = (const float*)d_in[2];
    const float* b1  = (const float*)d_in[3];
    const float* g1  = (const float*)d_in[4];
    const float* be1 = (const float*)d_in[5];
    const float* wd  = (const float*)d_in[6];
    const float* gd  = (const float*)d_in[7];
    const float* bed = (const float*)d_in[8];
    const float* w2  = (const float*)d_in[9];
    const float* b2  = (const float*)d_in[10];
    const float* g2  = (const float*)d_in[11];
    const float* be2 = (const float*)d_in[12];
    float* out = (float*)d_out;

    static int inited = 0;
    if (!inited) {
        cudaFuncSetAttribute(k_prep,   cudaFuncAttributeMaxDynamicSharedMemorySize, PREP_SMEM);
        cudaFuncSetAttribute(k_gemm2f, cudaFuncAttributeMaxDynamicSharedMemorySize, G2_SMEM);
        inited = 1;
    }

    void* p_z;
    cudaGetSymbolAddress(&p_z, g_z);
    cudaMemsetAsync(p_z, 0, sizeof(ZScratch));

    k_prep  <<<384, 256, PREP_SMEM>>>(x, pos, w1, b1);
    k_gemm1f<<<dim3(NPTS/64, MM/64, BB), 128>>>(x, w1, b1, g1, be1, wd);
    k_gather<<<BB*NPTS/8, 256>>>(wd, gd, bed);
    k_gemm2f<<<256, 256, G2_SMEM>>>(w2, b2, x, g2, be2, out);
}

// round 16
// speedup vs baseline: 1.2383x; 1.2383x over previous
#include <cuda_runtime.h>
#include <cuda_fp16.h>
#include <math.h>

#define BB 2
#define CC 64
#define NPTS 4096
#define MM 256
#define NS 32
#define R2 0.04f

// -------- scratch (device globals; no allocation allowed) --------
struct ZScratch {
    float  G[BB*CC*CC];
    float  sv[BB*CC];
    double stat[48];      // s1[8],ss1[8],s2[8],ss2[8],s3[8],ss3[8]
    int    bar;
    int    bar2;
    int    cnt[BB*NPTS];
};
__device__ ZScratch g_z;

__device__ int     g_idx[BB*NPTS*NS];
__device__ __half2 g_featsh[BB*NPTS*(MM/2)];  // (B, N, M/2) fp16 pairs
__device__ __half2 g_h2[BB*NPTS*(MM/2)];      // (B, N, M/2) fp16 pairs

#define G_S1  (g_z.stat)
#define G_SS1 (g_z.stat + 8)
#define G_S2  (g_z.stat + 16)
#define G_SS2 (g_z.stat + 24)
#define G_S3  (g_z.stat + 32)
#define G_SS3 (g_z.stat + 40)

__device__ __forceinline__ float gelu_f(float v) {
    return 0.5f * v * (1.0f + erff(v * 0.70710678118654752f));
}

__device__ __forceinline__ void mma16816(float* d, const unsigned* a,
                                         const unsigned* bf, const float* c) {
    asm volatile(
        "mma.sync.aligned.m16n8k16.row.col.f32.f16.f16.f32 "
        "{%0,%1,%2,%3}, {%4,%5,%6,%7}, {%8,%9}, {%10,%11,%12,%13};"
        : "=f"(d[0]), "=f"(d[1]), "=f"(d[2]), "=f"(d[3])
        : "r"(a[0]), "r"(a[1]), "r"(a[2]), "r"(a[3]),
          "r"(bf[0]), "r"(bf[1]),
          "f"(c[0]), "f"(c[1]), "f"(c[2]), "f"(c[3]));
}

// -------- K1: prep = gram+GN1stats (blocks 0-127) || ball query (blocks 128-383) ----
#define PREP_SMEM 50176
__global__ void __launch_bounds__(256, 4) k_prep(const float* __restrict__ x,
                                                 const float* __restrict__ pos,
                                                 const float* __restrict__ w1,
                                                 const float* __restrict__ b1) {
    extern __shared__ char smu[];
    int tid = threadIdx.x;
    int blk = blockIdx.x;
    int warp = tid >> 5, lane = tid & 31;

    if (blk >= 128) {
        float* sx = (float*)smu;
        float* sy = sx + NPTS;
        float* sz = sy + NPTS;
        int*   widx = (int*)(smu + 49152);
        int idx = blk - 128;
        int b = idx >> 7, nbase = (idx & 127) * 32;
        const float* pb = pos + b * 3 * NPTS;
        for (int i = tid; i < NPTS; i += 256) {
            sx[i] = pb[i];
            sy[i] = pb[NPTS + i];
            sz[i] = pb[2*NPTS + i];
        }
        __syncthreads();

        int* wl = widx + warp * NS;
        for (int r = 0; r < 4; r++) {
            int n = nbase + warp*4 + r;
            float xn = sx[n], yn = sy[n], zn = sz[n];
            float sqn = xn*xn + yn*yn + zn*zn;
            int cnt = 0, firstm = -1;
            for (int base = 0; base < NPTS && cnt < NS; base += 32) {
                int mq = base + lane;
                float xm = sx[mq], ym = sy[mq], zm = sz[mq];
                float sqm = xm*xm + ym*ym + zm*zm;
                float dot = xn*xm + yn*ym + zn*zm;
                float d = sqn + sqm - 2.0f * dot;
                bool q = !(d > R2);
                unsigned mask = __ballot_sync(0xffffffffu, q);
                if (mask) {
                    if (firstm < 0) firstm = base + __ffs(mask) - 1;
                    int nq = __popc(mask);
                    int slots = NS - cnt;
                    if (q) {
                        int rank = __popc(mask & ((1u << lane) - 1u));
                        if (rank < slots) wl[cnt + rank] = mq;
                    }
                    cnt += (nq < slots) ? nq : slots;
                }
            }
            __syncwarp();
            if (lane >= cnt) wl[lane] = firstm;
            __syncwarp();
            int j = wl[lane];
            g_idx[(b*NPTS + n)*NS + lane] = j;
            atomicAdd(&g_z.cnt[b*NPTS + j], 1);
            __syncwarp();
        }
        return;
    }

    {
        float* sA = (float*)smu;          // [c][n] pitch 68
        int b = blk >> 6, n0 = (blk & 63) * 64;
        for (int e = tid; e < 4096; e += 256) {
            int c = e >> 6, nn = e & 63;
            sA[c*68 + nn] = x[(b*CC + c)*NPTS + n0 + nn];
        }
        __syncthreads();

        int tx = tid & 15, ty = tid >> 4;
        float acc[4][4] = {};
#pragma unroll 16
        for (int k = 0; k < 64; k++) {
            float a[4], h[4];
#pragma unroll
            for (int i = 0; i < 4; i++) a[i] = sA[(ty*4 + i)*68 + k];
#pragma unroll
            for (int j = 0; j < 4; j++) h[j] = sA[(tx*4 + j)*68 + k];
#pragma unroll
            for (int i = 0; i < 4; i++)
#pragma unroll
                for (int j = 0; j < 4; j++)
                    acc[i][j] = fmaf(a[i], h[j], acc[i][j]);
        }
        float* Gb = g_z.G + b*CC*CC;
#pragma unroll
        for (int i = 0; i < 4; i++)
#pragma unroll
            for (int j = 0; j < 4; j++)
                atomicAdd(&Gb[(ty*4 + i)*CC + tx*4 + j], acc[i][j]);
        if (tid < CC) {
            float s = 0.f;
#pragma unroll
            for (int nn = 0; nn < 64; nn++) s += sA[tid*68 + nn];
            atomicAdd(&g_z.sv[b*CC + tid], s);
        }
    }

    __syncthreads();
    __threadfence();
    if (tid == 0) atomicAdd(&g_z.bar, 1);
    if (blk >= 8) return;

    if (tid == 0) {
        while (atomicAdd(&g_z.bar, 0) < 128) __nanosleep(128);
    }
    __syncthreads();

    {
        float* sG  = (float*)smu;
        float* sw  = (float*)(smu + 16384);
        float* ssv = (float*)(smu + 33024);
        double* sd  = (double*)(smu + 33280);
        double* ssd = (double*)(smu + 33792);
        int bg = blk;
        int sb = bg >> 2, m0 = (bg & 3) * 64;
        for (int e = tid; e < CC*CC; e += 256) sG[e] = __ldcg(&g_z.G[sb*CC*CC + e]);
        for (int e = tid; e < 64*CC; e += 256) sw[(e >> 6)*65 + (e & 63)] = w1[(m0 + (e >> 6))*CC + (e & 63)];
        if (tid < CC) ssv[tid] = __ldcg(&g_z.sv[sb*CC + tid]);
        __syncthreads();

        int mi = tid >> 2, part = tid & 3;
        float q = 0.f, l = 0.f;
        const float* wrow = sw + mi*65;
#pragma unroll
        for (int cc = 0; cc < 16; cc++) {
            int c = part*16 + cc;
            float wc = wrow[c];
            float in0 = 0.f, in1 = 0.f;
#pragma unroll
            for (int c2 = 0; c2 < 64; c2 += 2) {
                in0 = fmaf(wrow[c2],   sG[c*CC + c2],   in0);
                in1 = fmaf(wrow[c2+1], sG[c*CC + c2+1], in1);
            }
            q = fmaf(wc, in0 + in1, q);
            l = fmaf(wc, ssv[c], l);
        }
        q += __shfl_down_sync(0xffffffffu, q, 1);
        q += __shfl_down_sync(0xffffffffu, q, 2);
        l += __shfl_down_sync(0xffffffffu, l, 1);
        l += __shfl_down_sync(0xffffffffu, l, 2);
        if (part == 0) {
            double bb = (double)b1[m0 + mi];
            sd[mi]  = (double)l + 4096.0 * bb;
            ssd[mi] = (double)q + 2.0 * bb * (double)l + 4096.0 * bb * bb;
        }
        __syncthreads();
        for (int s = 32; s > 0; s >>= 1) {
            if (tid < s) { sd[tid] += sd[tid + s]; ssd[tid] += ssd[tid + s]; }
            __syncthreads();
        }
        if (tid == 0) { G_S1[bg] = sd[0]; G_SS1[bg] = ssd[0]; }
    }
}

// -------- K2: GEMM1 (64m x 64n tile, 8m x 4n thread, 128 threads) + GN1 + GELU
//          + fp16 feats + count-weighted GN2 stats --------
__global__ void k_gemm1f(const float* __restrict__ x, const float* __restrict__ w1,
                         const float* __restrict__ b1, const float* __restrict__ g1,
                         const float* __restrict__ be1, const float* __restrict__ wd) {
    __shared__ float sWt[64*68];
    __shared__ float sX[64*64];
    __shared__ float red1[128], red2[128];
    int b = blockIdx.z, m0 = blockIdx.y * 64, n0 = blockIdx.x * 64;
    int tid = threadIdx.x;
    int bg = b*4 + blockIdx.y;

    for (int e = tid; e < 4096; e += 128) {
        int m = e >> 6, c = e & 63;
        sWt[c*68 + m] = w1[(m0 + m)*CC + c];
    }
    for (int e = tid; e < 4096; e += 128) {
        int c = e >> 6, nn = e & 63;
        sX[c*64 + nn] = x[(b*CC + c)*NPTS + n0 + nn];
    }
    __syncthreads();

    int tx = tid & 15, ty = tid >> 4;
    float acc[8][4] = {};
#pragma unroll 8
    for (int k = 0; k < 64; k++) {
        float4 a0 = *(float4*)&sWt[k*68 + ty*8];
        float4 a1 = *(float4*)&sWt[k*68 + ty*8 + 4];
        float4 h4 = *(float4*)&sX[k*64 + tx*4];
        float a[8] = {a0.x, a0.y, a0.z, a0.w, a1.x, a1.y, a1.z, a1.w};
        float h[4] = {h4.x, h4.y, h4.z, h4.w};
#pragma unroll
        for (int i = 0; i < 8; i++)
#pragma unroll
            for (int j = 0; j < 4; j++)
                acc[i][j] = fmaf(a[i], h[j], acc[i][j]);
    }

    double mean = __ldcg(&G_S1[bg]) * (1.0 / (64.0 * 4096.0));
    double var  = __ldcg(&G_SS1[bg]) * (1.0 / (64.0 * 4096.0)) - mean * mean;
    float rs = (float)rsqrt(var + 1e-5);
    float mn = (float)mean;

    float ga[8], bo[8], wm[8];
#pragma unroll
    for (int i = 0; i < 8; i++) {
        int m = m0 + ty*8 + i;
        float bb = b1[m];
        ga[i] = g1[m] * rs;
        bo[i] = be1[m] - (mn - bb) * ga[i];
        wm[i] = wd[m];
    }
    float w[4];
#pragma unroll
    for (int j = 0; j < 4; j++) w[j] = (float)__ldcg(&g_z.cnt[b*NPTS + n0 + tx*4 + j]);

    float lsum = 0.f, lss = 0.f;
#pragma unroll
    for (int j = 0; j < 4; j++) {
        __half2 hv[4];
#pragma unroll
        for (int p = 0; p < 4; p++) {
            float v0 = gelu_f(fmaf(acc[2*p][j],   ga[2*p],   bo[2*p]));
            float v1 = gelu_f(fmaf(acc[2*p+1][j], ga[2*p+1], bo[2*p+1]));
            hv[p] = __floats2half2_rn(v0, v1);
            float a0 = v0 * wm[2*p], a1 = v1 * wm[2*p+1];
            lsum = fmaf(w[j], a0 + a1, lsum);
            lss  = fmaf(w[j], a0*a0 + a1*a1, lss);
        }
        int n = n0 + tx*4 + j;
        __half2* dst = g_featsh + (size_t)(b*NPTS + n)*(MM/2) + (m0 >> 1) + ty*4;
        *(uint4*)dst = *(uint4*)hv;
    }

    red1[tid] = lsum; red2[tid] = lss;
    __syncthreads();
    for (int s = 64; s > 0; s >>= 1) {
        if (tid < s) { red1[tid] += red1[tid + s]; red2[tid] += red2[tid + s]; }
        __syncthreads();
    }
    if (tid == 0) {
        atomicAdd(&G_S2[bg],  (double)red1[0]);
        atomicAdd(&G_SS2[bg], (double)red2[0]);
    }
}

// -------- K3: gather (warp per point, uint4 loads) + GN2 + maxpool + GELU -> h2 fp16 --------
__global__ void k_gather(const float* __restrict__ wd, const float* __restrict__ gd,
                         const float* __restrict__ bed) {
    __shared__ float sA[MM], sBc[MM];
    __shared__ int sI[8*NS];
    int blk = blockIdx.x;
    int b = blk >> 9, n0 = (blk & 511) * 8;
    int tid = threadIdx.x;

    {
        int m = tid;
        int bg = b*4 + (m >> 6);
        double mean = G_S2[bg] * (1.0 / 8388608.0);
        double var  = G_SS2[bg] * (1.0 / 8388608.0) - mean * mean;
        float rsv = (float)rsqrt(var + 1e-5);
        sA[m]  = wd[m] * rsv * gd[m];
        sBc[m] = bed[m] - (float)((double)rsv * mean) * gd[m];
    }
    sI[tid] = g_idx[(b*NPTS + n0)*NS + tid];
    __syncthreads();

    int warp = tid >> 5, lane = tid & 31;
    int n = n0 + warp;
    const int* il = sI + warp * NS;
    const uint4* fb = ((const uint4*)(g_featsh + (size_t)b*NPTS*(MM/2))) + lane;

    __half2 hneg = __half2half2(__float2half(-65504.f));
    __half2 hpos = __half2half2(__float2half( 65504.f));
    __half2 mxA[4] = {hneg, hneg, hneg, hneg};
    __half2 mnA[4] = {hpos, hpos, hpos, hpos};
    __half2 mxB[4] = {hneg, hneg, hneg, hneg};
    __half2 mnB[4] = {hpos, hpos, hpos, hpos};

#pragma unroll
    for (int s = 0; s < NS; s += 2) {
        uint4 va = fb[(size_t)il[s]   * 32];
        uint4 vb = fb[(size_t)il[s+1] * 32];
        const __half2* ha = (const __half2*)&va;
        const __half2* hb = (const __half2*)&vb;
#pragma unroll
        for (int u = 0; u < 4; u++) {
            mxA[u] = __hmax2(mxA[u], ha[u]); mnA[u] = __hmin2(mnA[u], ha[u]);
            mxB[u] = __hmax2(mxB[u], hb[u]); mnB[u] = __hmin2(mnB[u], hb[u]);
        }
    }

    __half2 outv[4];
#pragma unroll
    for (int u = 0; u < 4; u++) {
        float2 fmx = __half22float2(__hmax2(mxA[u], mxB[u]));
        float2 fmn = __half22float2(__hmin2(mnA[u], mnB[u]));
        int ch = 8*lane + 2*u;
        float A0 = sA[ch],   B0 = sBc[ch];
        float A1 = sA[ch+1], B1 = sBc[ch+1];
        float v0 = (A0 >= 0.f) ? fmx.x : fmn.x;
        float v1 = (A1 >= 0.f) ? fmx.y : fmn.y;
        float r0 = gelu_f(fmaf(A0, v0, B0));
        float r1 = gelu_f(fmaf(A1, v1, B1));
        outv[u] = __floats2half2_rn(r0, r1);
    }
    ((uint4*)(g_h2 + (size_t)(b*NPTS + n)*(MM/2)))[lane] = *(uint4*)outv;
}

// -------- K4: GEMM2 via mma.sync (64c x 32n block, 8 warps, m16n8k16 HMMA)
//          + GN3 stats + barrier + apply + residual ----
// grid 256, 256 threads; dyn smem 50688 B -> >=4 CTAs/SM capacity -> barrier safe
#define G2_PITCH 264
#define G2_SMEM ((64 + 32) * G2_PITCH * 2)
__global__ void __launch_bounds__(256, 4) k_gemm2f(
    const float* __restrict__ w2, const float* __restrict__ b2,
    const float* __restrict__ x,  const float* __restrict__ g2,
    const float* __restrict__ be2, float* __restrict__ out) {
    extern __shared__ char smc[];
    __half* sW2h = (__half*)smc;                           // A: [c][k] pitch 264
    __half* sHn  = (__half*)(smc + 64*G2_PITCH*2);         // B: [n][k] pitch 264
    __shared__ float sacc[4], sss[4];
    __shared__ float sMean[4], sRs[4];

    int blk = blockIdx.x;
    int b = blk >> 7, n0 = (blk & 127) * 32;
    int tid = threadIdx.x;
    if (tid < 4) { sacc[tid] = 0.f; sss[tid] = 0.f; }

    // ---- stage w2 -> fp16 [c][k] ----
    for (int e = tid; e < 4096; e += 256) {
        int c = e >> 6, kq = e & 63;
        float4 v = *(const float4*)&w2[c*MM + kq*4];
        __half2 p0 = __floats2half2_rn(v.x, v.y);
        __half2 p1 = __floats2half2_rn(v.z, v.w);
        *(__half2*)&sW2h[c*G2_PITCH + 4*kq]     = p0;
        *(__half2*)&sW2h[c*G2_PITCH + 4*kq + 2] = p1;
    }
    // ---- stage h2 -> fp16 [n][k] ----
    for (int e = tid; e < 4096; e += 256) {
        int n = e >> 7, mp = e & 127;
        __half2 v = g_h2[(size_t)(b*NPTS + n0 + n)*(MM/2) + mp];
        *(__half2*)&sHn[n*G2_PITCH + 2*mp] = v;
    }
    __syncthreads();

    int warp = tid >> 5, lane = tid & 31;
    int g = lane >> 2, t = lane & 3;
    int cw = (warp & 3) * 16;       // c chunk
    int nh = (warp >> 2) * 16;      // n half

    float acc0[4] = {0.f, 0.f, 0.f, 0.f};
    float acc1[4] = {0.f, 0.f, 0.f, 0.f};
    const __half* Arow0 = sW2h + (cw + g) * G2_PITCH;
    const __half* Arow1 = sW2h + (cw + g + 8) * G2_PITCH;
    const __half* Brow0 = sHn + (nh + g) * G2_PITCH;
    const __half* Brow1 = sHn + (nh + 8 + g) * G2_PITCH;

#pragma unroll
    for (int ks = 0; ks < 16; ks++) {
        int k0 = ks * 16 + 2 * t;
        unsigned a[4], bf0[2], bf1[2];
        a[0] = *(const unsigned*)&Arow0[k0];
        a[1] = *(const unsigned*)&Arow1[k0];
        a[2] = *(const unsigned*)&Arow0[k0 + 8];
        a[3] = *(const unsigned*)&Arow1[k0 + 8];
        bf0[0] = *(const unsigned*)&Brow0[k0];
        bf0[1] = *(const unsigned*)&Brow0[k0 + 8];
        bf1[0] = *(const unsigned*)&Brow1[k0];
        bf1[1] = *(const unsigned*)&Brow1[k0 + 8];
        mma16816(acc0, a, bf0, acc0);
        mma16816(acc1, a, bf1, acc1);
    }

    // bias + stats (warp's 16 c's are all in group warp&3)
    float bz0 = b2[cw + g], bz1 = b2[cw + g + 8];
    float v00 = acc0[0] + bz0, v01 = acc0[1] + bz0;
    float v02 = acc0[2] + bz1, v03 = acc0[3] + bz1;
    float v10 = acc1[0] + bz0, v11 = acc1[1] + bz0;
    float v12 = acc1[2] + bz1, v13 = acc1[3] + bz1;

    float lsum = v00+v01+v02+v03+v10+v11+v12+v13;
    float lss  = v00*v00+v01*v01+v02*v02+v03*v03+v10*v10+v11*v11+v12*v12+v13*v13;
#pragma unroll
    for (int o = 16; o > 0; o >>= 1) {
        lsum += __shfl_down_sync(0xffffffffu, lsum, o);
        lss  += __shfl_down_sync(0xffffffffu, lss,  o);
    }
    if (lane == 0) {
        atomicAdd(&sacc[warp & 3], lsum);
        atomicAdd(&sss[warp & 3],  lss);
    }
    __syncthreads();
    if (tid < 4) {
        atomicAdd(&G_S3[b*4 + tid],  (double)sacc[tid]);
        atomicAdd(&G_SS3[b*4 + tid], (double)sss[tid]);
        __threadfence();
    }
    __syncthreads();

    if (tid == 0) {
        atomicAdd(&g_z.bar2, 1);
        while (atomicAdd(&g_z.bar2, 0) < 256) __nanosleep(128);
    }
    __syncthreads();

    if (tid < 4) {
        double s  = atomicAdd(&G_S3[b*4 + tid],  0.0);
        double ss = atomicAdd(&G_SS3[b*4 + tid], 0.0);
        double mean = s * (1.0 / 65536.0);
        double var  = ss * (1.0 / 65536.0) - mean * mean;
        sMean[tid] = (float)mean;
        sRs[tid]   = (float)rsqrt(var + 1e-5);
    }
    __syncthreads();

    // apply GN3 + residual; thread writes 4 float2 (rows g/g+8 x 2 n-tiles)
    {
        int gg = warp & 3;
        float ga0 = sRs[gg] * g2[cw + g];
        float bo0 = be2[cw + g] - sMean[gg] * ga0;
        float ga1 = sRs[gg] * g2[cw + g + 8];
        float bo1 = be2[cw + g + 8] - sMean[gg] * ga1;

        size_t r0 = (size_t)(b*CC + cw + g)*NPTS + n0;
        size_t r1 = (size_t)(b*CC + cw + g + 8)*NPTS + n0;
        int col0 = nh + 2*t, col1 = nh + 8 + 2*t;

        float2 xv, ov;
        xv = *(const float2*)&x[r0 + col0];
        ov.x = fmaf(v00, ga0, bo0) + xv.x; ov.y = fmaf(v01, ga0, bo0) + xv.y;
        *(float2*)&out[r0 + col0] = ov;
        xv = *(const float2*)&x[r1 + col0];
        ov.x = fmaf(v02, ga1, bo1) + xv.x; ov.y = fmaf(v03, ga1, bo1) + xv.y;
        *(float2*)&out[r1 + col0] = ov;
        xv = *(const float2*)&x[r0 + col1];
        ov.x = fmaf(v10, ga0, bo0) + xv.x; ov.y = fmaf(v11, ga0, bo0) + xv.y;
        *(float2*)&out[r0 + col1] = ov;
        xv = *(const float2*)&x[r1 + col1];
        ov.x = fmaf(v12, ga1, bo1) + xv.x; ov.y = fmaf(v13, ga1, bo1) + xv.y;
        *(float2*)&out[r1 + col1] = ov;
    }
}

extern "C" void kernel_launch(void* const* d_in, const int* in_sizes, int n_in,
                              void* d_out, int out_size) {
    const float* x   = (const float*)d_in[0];
    const float* pos = (const float*)d_in[1];
    const float* w1  = (const float*)d_in[2];
    const float* b1  = (const float*)d_in[3];
    const float* g1  = (const float*)d_in[4];
    const float* be1 = (const float*)d_in[5];
    const float* wd  = (const float*)d_in[6];
    const float* gd  = (const float*)d_in[7];
    const float* bed = (const float*)d_in[8];
    const float* w2  = (const float*)d_in[9];
    const float* b2  = (const float*)d_in[10];
    const float* g2  = (const float*)d_in[11];
    const float* be2 = (const float*)d_in[12];
    float* out = (float*)d_out;

    static int inited = 0;
    if (!inited) {
        cudaFuncSetAttribute(k_prep,   cudaFuncAttributeMaxDynamicSharedMemorySize, PREP_SMEM);
        cudaFuncSetAttribute(k_gemm2f, cudaFuncAttributeMaxDynamicSharedMemorySize, G2_SMEM);
        inited = 1;
    }

    void* p_z;
    cudaGetSymbolAddress(&p_z, g_z);
    cudaMemsetAsync(p_z, 0, sizeof(ZScratch));

    k_prep  <<<384, 256, PREP_SMEM>>>(x, pos, w1, b1);
    k_gemm1f<<<dim3(NPTS/64, MM/64, BB), 128>>>(x, w1, b1, g1, be1, wd);
    k_gather<<<BB*NPTS/8, 256>>>(wd, gd, bed);
    k_gemm2f<<<256, 256, G2_SMEM>>>(w2, b2, x, g2, be2, out);
}

// round 17
// speedup vs baseline: 1.2956x; 1.0463x over previous
#include <cuda_runtime.h>
#include <cuda_fp16.h>
#include <math.h>

#define BB 2
#define CC 64
#define NPTS 4096
#define MM 256
#define NS 32
#define R2 0.04f

// -------- scratch (device globals; no allocation allowed) --------
struct ZScratch {
    float  G[BB*CC*CC];
    float  sv[BB*CC];
    double stat[48];      // s1[8],ss1[8],s2[8],ss2[8],s3[8],ss3[8]
    int    bar;
    int    bar2;
    int    cnt[BB*NPTS];
};
__device__ ZScratch g_z;

__device__ int     g_idx[BB*NPTS*NS];
__device__ __half2 g_featsh[BB*NPTS*(MM/2)];  // (B, N, M/2) fp16 pairs
__device__ __half2 g_h2[BB*NPTS*(MM/2)];      // (B, N, M/2) fp16 pairs

#define G_S1  (g_z.stat)
#define G_SS1 (g_z.stat + 8)
#define G_S2  (g_z.stat + 16)
#define G_SS2 (g_z.stat + 24)
#define G_S3  (g_z.stat + 32)
#define G_SS3 (g_z.stat + 40)

__device__ __forceinline__ float gelu_f(float v) {
    return 0.5f * v * (1.0f + erff(v * 0.70710678118654752f));
}

__device__ __forceinline__ void mma16816(float* d, const unsigned* a,
                                         const unsigned* bf, const float* c) {
    asm volatile(
        "mma.sync.aligned.m16n8k16.row.col.f32.f16.f16.f32 "
        "{%0,%1,%2,%3}, {%4,%5,%6,%7}, {%8,%9}, {%10,%11,%12,%13};"
        : "=f"(d[0]), "=f"(d[1]), "=f"(d[2]), "=f"(d[3])
        : "r"(a[0]), "r"(a[1]), "r"(a[2]), "r"(a[3]),
          "r"(bf[0]), "r"(bf[1]),
          "f"(c[0]), "f"(c[1]), "f"(c[2]), "f"(c[3]));
}

// -------- K1: prep = gram+GN1stats (blocks 0-127) || ball query (blocks 128-383) ----
#define PREP_SMEM 50176
__global__ void __launch_bounds__(256, 4) k_prep(const float* __restrict__ x,
                                                 const float* __restrict__ pos,
                                                 const float* __restrict__ w1,
                                                 const float* __restrict__ b1) {
    extern __shared__ char smu[];
    int tid = threadIdx.x;
    int blk = blockIdx.x;
    int warp = tid >> 5, lane = tid & 31;

    if (blk >= 128) {
        float* sx = (float*)smu;
        float* sy = sx + NPTS;
        float* sz = sy + NPTS;
        int*   widx = (int*)(smu + 49152);
        int idx = blk - 128;
        int b = idx >> 7, nbase = (idx & 127) * 32;
        const float* pb = pos + b * 3 * NPTS;
        for (int i = tid; i < NPTS; i += 256) {
            sx[i] = pb[i];
            sy[i] = pb[NPTS + i];
            sz[i] = pb[2*NPTS + i];
        }
        __syncthreads();

        int* wl = widx + warp * NS;
        for (int r = 0; r < 4; r++) {
            int n = nbase + warp*4 + r;
            float xn = sx[n], yn = sy[n], zn = sz[n];
            float sqn = xn*xn + yn*yn + zn*zn;
            int cnt = 0, firstm = -1;
            for (int base = 0; base < NPTS && cnt < NS; base += 32) {
                int mq = base + lane;
                float xm = sx[mq], ym = sy[mq], zm = sz[mq];
                float sqm = xm*xm + ym*ym + zm*zm;
                float dot = xn*xm + yn*ym + zn*zm;
                float d = sqn + sqm - 2.0f * dot;
                bool q = !(d > R2);
                unsigned mask = __ballot_sync(0xffffffffu, q);
                if (mask) {
                    if (firstm < 0) firstm = base + __ffs(mask) - 1;
                    int nq = __popc(mask);
                    int slots = NS - cnt;
                    if (q) {
                        int rank = __popc(mask & ((1u << lane) - 1u));
                        if (rank < slots) wl[cnt + rank] = mq;
                    }
                    cnt += (nq < slots) ? nq : slots;
                }
            }
            __syncwarp();
            if (lane >= cnt) wl[lane] = firstm;
            __syncwarp();
            int j = wl[lane];
            g_idx[(b*NPTS + n)*NS + lane] = j;
            atomicAdd(&g_z.cnt[b*NPTS + j], 1);
            __syncwarp();
        }
        return;
    }

    {
        float* sA = (float*)smu;          // [c][n] pitch 68
        int b = blk >> 6, n0 = (blk & 63) * 64;
        for (int e = tid; e < 4096; e += 256) {
            int c = e >> 6, nn = e & 63;
            sA[c*68 + nn] = x[(b*CC + c)*NPTS + n0 + nn];
        }
        __syncthreads();

        int tx = tid & 15, ty = tid >> 4;
        float acc[4][4] = {};
#pragma unroll 16
        for (int k = 0; k < 64; k++) {
            float a[4], h[4];
#pragma unroll
            for (int i = 0; i < 4; i++) a[i] = sA[(ty*4 + i)*68 + k];
#pragma unroll
            for (int j = 0; j < 4; j++) h[j] = sA[(tx*4 + j)*68 + k];
#pragma unroll
            for (int i = 0; i < 4; i++)
#pragma unroll
                for (int j = 0; j < 4; j++)
                    acc[i][j] = fmaf(a[i], h[j], acc[i][j]);
        }
        float* Gb = g_z.G + b*CC*CC;
#pragma unroll
        for (int i = 0; i < 4; i++)
#pragma unroll
            for (int j = 0; j < 4; j++)
                atomicAdd(&Gb[(ty*4 + i)*CC + tx*4 + j], acc[i][j]);
        if (tid < CC) {
            float s = 0.f;
#pragma unroll
            for (int nn = 0; nn < 64; nn++) s += sA[tid*68 + nn];
            atomicAdd(&g_z.sv[b*CC + tid], s);
        }
    }

    __syncthreads();
    __threadfence();
    if (tid == 0) atomicAdd(&g_z.bar, 1);
    if (blk >= 8) return;

    if (tid == 0) {
        while (atomicAdd(&g_z.bar, 0) < 128) __nanosleep(128);
    }
    __syncthreads();

    {
        float* sG  = (float*)smu;
        float* sw  = (float*)(smu + 16384);
        float* ssv = (float*)(smu + 33024);
        double* sd  = (double*)(smu + 33280);
        double* ssd = (double*)(smu + 33792);
        int bg = blk;
        int sb = bg >> 2, m0 = (bg & 3) * 64;
        for (int e = tid; e < CC*CC; e += 256) sG[e] = __ldcg(&g_z.G[sb*CC*CC + e]);
        for (int e = tid; e < 64*CC; e += 256) sw[(e >> 6)*65 + (e & 63)] = w1[(m0 + (e >> 6))*CC + (e & 63)];
        if (tid < CC) ssv[tid] = __ldcg(&g_z.sv[sb*CC + tid]);
        __syncthreads();

        int mi = tid >> 2, part = tid & 3;
        float q = 0.f, l = 0.f;
        const float* wrow = sw + mi*65;
#pragma unroll
        for (int cc = 0; cc < 16; cc++) {
            int c = part*16 + cc;
            float wc = wrow[c];
            float in0 = 0.f, in1 = 0.f;
#pragma unroll
            for (int c2 = 0; c2 < 64; c2 += 2) {
                in0 = fmaf(wrow[c2],   sG[c*CC + c2],   in0);
                in1 = fmaf(wrow[c2+1], sG[c*CC + c2+1], in1);
            }
            q = fmaf(wc, in0 + in1, q);
            l = fmaf(wc, ssv[c], l);
        }
        q += __shfl_down_sync(0xffffffffu, q, 1);
        q += __shfl_down_sync(0xffffffffu, q, 2);
        l += __shfl_down_sync(0xffffffffu, l, 1);
        l += __shfl_down_sync(0xffffffffu, l, 2);
        if (part == 0) {
            double bb = (double)b1[m0 + mi];
            sd[mi]  = (double)l + 4096.0 * bb;
            ssd[mi] = (double)q + 2.0 * bb * (double)l + 4096.0 * bb * bb;
        }
        __syncthreads();
        for (int s = 32; s > 0; s >>= 1) {
            if (tid < s) { sd[tid] += sd[tid + s]; ssd[tid] += ssd[tid + s]; }
            __syncthreads();
        }
        if (tid == 0) { G_S1[bg] = sd[0]; G_SS1[bg] = ssd[0]; }
    }
}

// -------- K2: GEMM1 via mma.sync (64m x 64n block, 8 warps) + GN1 + GELU
//          + fp16 feats + count-weighted GN2 stats --------
__global__ void __launch_bounds__(256) k_gemm1f(
    const float* __restrict__ x, const float* __restrict__ w1,
    const float* __restrict__ b1, const float* __restrict__ g1,
    const float* __restrict__ be1, const float* __restrict__ wd) {
    __shared__ __half sW1h[64*72];    // A: [m][k] pitch 72; reused as sOut [n][m] after loop
    __shared__ __half sXh[64*72];     // B: [n][k] pitch 72
    __shared__ float sGa[64], sBo[64], sWm[64], sCnt[64];
    __shared__ float red1[256], red2[256];

    int b = blockIdx.z, m0 = blockIdx.y * 64, n0 = blockIdx.x * 64;
    int tid = threadIdx.x;
    int warp = tid >> 5, lane = tid & 31;
    int bg = b*4 + blockIdx.y;

    // GN1 affine coeffs into smem
    {
        double mean = __ldcg(&G_S1[bg]) * (1.0 / (64.0 * 4096.0));
        double var  = __ldcg(&G_SS1[bg]) * (1.0 / (64.0 * 4096.0)) - mean * mean;
        float rs = (float)rsqrt(var + 1e-5);
        float mn = (float)mean;
        if (tid < 64) {
            int m = m0 + tid;
            float bb = b1[m];
            float ga = g1[m] * rs;
            sGa[tid] = ga;
            sBo[tid] = be1[m] - (mn - bb) * ga;
            sWm[tid] = wd[m];
        } else if (tid < 128) {
            sCnt[tid - 64] = (float)__ldcg(&g_z.cnt[b*NPTS + n0 + tid - 64]);
        }
    }

    // stage w1 -> fp16 [m][k]
    for (int e = tid; e < 1024; e += 256) {
        int m = e >> 4, cq = e & 15;
        float4 v = *(const float4*)&w1[(m0 + m)*CC + cq*4];
        *(__half2*)&sW1h[m*72 + cq*4]     = __floats2half2_rn(v.x, v.y);
        *(__half2*)&sW1h[m*72 + cq*4 + 2] = __floats2half2_rn(v.z, v.w);
    }
    // stage x -> fp16 transposed [n][k]
    for (int e = tid; e < 1024; e += 256) {
        int c = e >> 4, nq = e & 15;
        float4 v = *(const float4*)&x[(size_t)(b*CC + c)*NPTS + n0 + nq*4];
        sXh[(nq*4 + 0)*72 + c] = __float2half_rn(v.x);
        sXh[(nq*4 + 1)*72 + c] = __float2half_rn(v.y);
        sXh[(nq*4 + 2)*72 + c] = __float2half_rn(v.z);
        sXh[(nq*4 + 3)*72 + c] = __float2half_rn(v.w);
    }
    __syncthreads();

    int g = lane >> 2, t = lane & 3;
    int mw = (warp & 3) * 16;       // m-chunk
    int nh = (warp >> 2) * 32;      // n-half

    float acc[4][4] = {{0.f}};
    const __half* A0 = sW1h + (mw + g) * 72;
    const __half* A1 = sW1h + (mw + g + 8) * 72;
#pragma unroll
    for (int ks = 0; ks < 4; ks++) {
        int k0 = ks*16 + 2*t;
        unsigned a[4];
        a[0] = *(const unsigned*)&A0[k0];
        a[1] = *(const unsigned*)&A1[k0];
        a[2] = *(const unsigned*)&A0[k0 + 8];
        a[3] = *(const unsigned*)&A1[k0 + 8];
#pragma unroll
        for (int tn = 0; tn < 4; tn++) {
            const __half* Br = sXh + (nh + tn*8 + g) * 72;
            unsigned bf[2];
            bf[0] = *(const unsigned*)&Br[k0];
            bf[1] = *(const unsigned*)&Br[k0 + 8];
            mma16816(acc[tn], a, bf, acc[tn]);
        }
    }

    __syncthreads();   // all warps done reading sW1h -> safe to alias as sOut
    __half* sOutH = sW1h;   // [n][m] pitch 72

    int m_a = mw + g, m_b = mw + g + 8;
    float ga_a = sGa[m_a], bo_a = sBo[m_a], wm_a = sWm[m_a];
    float ga_b = sGa[m_b], bo_b = sBo[m_b], wm_b = sWm[m_b];

    float lsum = 0.f, lss = 0.f;
#pragma unroll
    for (int tn = 0; tn < 4; tn++) {
        int nl = nh + tn*8 + 2*t;
        float w0 = sCnt[nl], w1c = sCnt[nl + 1];
        float v00 = gelu_f(fmaf(acc[tn][0], ga_a, bo_a));   // (m_a, nl)
        float v01 = gelu_f(fmaf(acc[tn][1], ga_a, bo_a));   // (m_a, nl+1)
        float v10 = gelu_f(fmaf(acc[tn][2], ga_b, bo_b));   // (m_b, nl)
        float v11 = gelu_f(fmaf(acc[tn][3], ga_b, bo_b));   // (m_b, nl+1)
        sOutH[nl*72 + m_a]       = __float2half_rn(v00);
        sOutH[(nl + 1)*72 + m_a] = __float2half_rn(v01);
        sOutH[nl*72 + m_b]       = __float2half_rn(v10);
        sOutH[(nl + 1)*72 + m_b] = __float2half_rn(v11);
        float a00 = v00 * wm_a, a01 = v01 * wm_a;
        float a10 = v10 * wm_b, a11 = v11 * wm_b;
        lsum += w0*(a00 + a10) + w1c*(a01 + a11);
        lss  += w0*(a00*a00 + a10*a10) + w1c*(a01*a01 + a11*a11);
    }
    __syncthreads();

    // write feats: 64 n-rows x 128 B; 4 threads per row, 32 B each
    {
        int nl = tid >> 2, seg = tid & 3;
        uint4 v0 = *(uint4*)&sOutH[nl*72 + seg*16];
        uint4 v1 = *(uint4*)&sOutH[nl*72 + seg*16 + 8];
        __half2* dst = g_featsh + (size_t)(b*NPTS + n0 + nl)*(MM/2) + (m0 >> 1) + seg*8;
        *(uint4*)dst       = v0;
        *(uint4*)(dst + 4) = v1;
    }

    red1[tid] = lsum; red2[tid] = lss;
    __syncthreads();
    for (int s = 128; s > 0; s >>= 1) {
        if (tid < s) { red1[tid] += red1[tid + s]; red2[tid] += red2[tid + s]; }
        __syncthreads();
    }
    if (tid == 0) {
        atomicAdd(&G_S2[bg],  (double)red1[0]);
        atomicAdd(&G_SS2[bg], (double)red2[0]);
    }
}

// -------- K3: gather (warp per point, uint4 loads) + GN2 + maxpool + GELU -> h2 fp16 --------
__global__ void k_gather(const float* __restrict__ wd, const float* __restrict__ gd,
                         const float* __restrict__ bed) {
    __shared__ float sA[MM], sBc[MM];
    __shared__ int sI[8*NS];
    int blk = blockIdx.x;
    int b = blk >> 9, n0 = (blk & 511) * 8;
    int tid = threadIdx.x;

    {
        int m = tid;
        int bg = b*4 + (m >> 6);
        double mean = G_S2[bg] * (1.0 / 8388608.0);
        double var  = G_SS2[bg] * (1.0 / 8388608.0) - mean * mean;
        float rsv = (float)rsqrt(var + 1e-5);
        sA[m]  = wd[m] * rsv * gd[m];
        sBc[m] = bed[m] - (float)((double)rsv * mean) * gd[m];
    }
    sI[tid] = g_idx[(b*NPTS + n0)*NS + tid];
    __syncthreads();

    int warp = tid >> 5, lane = tid & 31;
    int n = n0 + warp;
    const int* il = sI + warp * NS;
    const uint4* fb = ((const uint4*)(g_featsh + (size_t)b*NPTS*(MM/2))) + lane;

    __half2 hneg = __half2half2(__float2half(-65504.f));
    __half2 hpos = __half2half2(__float2half( 65504.f));
    __half2 mxA[4] = {hneg, hneg, hneg, hneg};
    __half2 mnA[4] = {hpos, hpos, hpos, hpos};
    __half2 mxB[4] = {hneg, hneg, hneg, hneg};
    __half2 mnB[4] = {hpos, hpos, hpos, hpos};

#pragma unroll
    for (int s = 0; s < NS; s += 2) {
        uint4 va = fb[(size_t)il[s]   * 32];
        uint4 vb = fb[(size_t)il[s+1] * 32];
        const __half2* ha = (const __half2*)&va;
        const __half2* hb = (const __half2*)&vb;
#pragma unroll
        for (int u = 0; u < 4; u++) {
            mxA[u] = __hmax2(mxA[u], ha[u]); mnA[u] = __hmin2(mnA[u], ha[u]);
            mxB[u] = __hmax2(mxB[u], hb[u]); mnB[u] = __hmin2(mnB[u], hb[u]);
        }
    }

    __half2 outv[4];
#pragma unroll
    for (int u = 0; u < 4; u++) {
        float2 fmx = __half22float2(__hmax2(mxA[u], mxB[u]));
        float2 fmn = __half22float2(__hmin2(mnA[u], mnB[u]));
        int ch = 8*lane + 2*u;
        float A0 = sA[ch],   B0 = sBc[ch];
        float A1 = sA[ch+1], B1 = sBc[ch+1];
        float v0 = (A0 >= 0.f) ? fmx.x : fmn.x;
        float v1 = (A1 >= 0.f) ? fmx.y : fmn.y;
        float r0 = gelu_f(fmaf(A0, v0, B0));
        float r1 = gelu_f(fmaf(A1, v1, B1));
        outv[u] = __floats2half2_rn(r0, r1);
    }
    ((uint4*)(g_h2 + (size_t)(b*NPTS + n)*(MM/2)))[lane] = *(uint4*)outv;
}

// -------- K4: GEMM2 via mma.sync (64c x 32n block, 8 warps, m16n8k16 HMMA)
//          + GN3 stats + barrier + apply + residual; x prefetched over barrier ----
#define G2_PITCH 264
#define G2_SMEM ((64 + 32) * G2_PITCH * 2)
__global__ void __launch_bounds__(256, 4) k_gemm2f(
    const float* __restrict__ w2, const float* __restrict__ b2,
    const float* __restrict__ x,  const float* __restrict__ g2,
    const float* __restrict__ be2, float* __restrict__ out) {
    extern __shared__ char smc[];
    __half* sW2h = (__half*)smc;                           // A: [c][k] pitch 264
    __half* sHn  = (__half*)(smc + 64*G2_PITCH*2);         // B: [n][k] pitch 264
    __shared__ float sacc[4], sss[4];
    __shared__ float sMean[4], sRs[4];

    int blk = blockIdx.x;
    int b = blk >> 7, n0 = (blk & 127) * 32;
    int tid = threadIdx.x;
    if (tid < 4) { sacc[tid] = 0.f; sss[tid] = 0.f; }

    for (int e = tid; e < 4096; e += 256) {
        int c = e >> 6, kq = e & 63;
        float4 v = *(const float4*)&w2[c*MM + kq*4];
        *(__half2*)&sW2h[c*G2_PITCH + 4*kq]     = __floats2half2_rn(v.x, v.y);
        *(__half2*)&sW2h[c*G2_PITCH + 4*kq + 2] = __floats2half2_rn(v.z, v.w);
    }
    for (int e = tid; e < 4096; e += 256) {
        int n = e >> 7, mp = e & 127;
        __half2 v = g_h2[(size_t)(b*NPTS + n0 + n)*(MM/2) + mp];
        *(__half2*)&sHn[n*G2_PITCH + 2*mp] = v;
    }
    __syncthreads();

    int warp = tid >> 5, lane = tid & 31;
    int g = lane >> 2, t = lane & 3;
    int cw = (warp & 3) * 16;
    int nh = (warp >> 2) * 16;

    float acc0[4] = {0.f, 0.f, 0.f, 0.f};
    float acc1[4] = {0.f, 0.f, 0.f, 0.f};
    const __half* Arow0 = sW2h + (cw + g) * G2_PITCH;
    const __half* Arow1 = sW2h + (cw + g + 8) * G2_PITCH;
    const __half* Brow0 = sHn + (nh + g) * G2_PITCH;
    const __half* Brow1 = sHn + (nh + 8 + g) * G2_PITCH;

#pragma unroll
    for (int ks = 0; ks < 16; ks++) {
        int k0 = ks * 16 + 2 * t;
        unsigned a[4], bf0[2], bf1[2];
        a[0] = *(const unsigned*)&Arow0[k0];
        a[1] = *(const unsigned*)&Arow1[k0];
        a[2] = *(const unsigned*)&Arow0[k0 + 8];
        a[3] = *(const unsigned*)&Arow1[k0 + 8];
        bf0[0] = *(const unsigned*)&Brow0[k0];
        bf0[1] = *(const unsigned*)&Brow0[k0 + 8];
        bf1[0] = *(const unsigned*)&Brow1[k0];
        bf1[1] = *(const unsigned*)&Brow1[k0 + 8];
        mma16816(acc0, a, bf0, acc0);
        mma16816(acc1, a, bf1, acc1);
    }

    float bz0 = b2[cw + g], bz1 = b2[cw + g + 8];
    float v00 = acc0[0] + bz0, v01 = acc0[1] + bz0;
    float v02 = acc0[2] + bz1, v03 = acc0[3] + bz1;
    float v10 = acc1[0] + bz0, v11 = acc1[1] + bz0;
    float v12 = acc1[2] + bz1, v13 = acc1[3] + bz1;

    // prefetch residual x (independent of barrier) so latency overlaps the spin
    size_t r0 = (size_t)(b*CC + cw + g)*NPTS + n0;
    size_t r1 = (size_t)(b*CC + cw + g + 8)*NPTS + n0;
    int col0 = nh + 2*t, col1 = nh + 8 + 2*t;
    float2 x00 = *(const float2*)&x[r0 + col0];
    float2 x01 = *(const float2*)&x[r1 + col0];
    float2 x10 = *(const float2*)&x[r0 + col1];
    float2 x11 = *(const float2*)&x[r1 + col1];

    float lsum = v00+v01+v02+v03+v10+v11+v12+v13;
    float lss  = v00*v00+v01*v01+v02*v02+v03*v03+v10*v10+v11*v11+v12*v12+v13*v13;
#pragma unroll
    for (int o = 16; o > 0; o >>= 1) {
        lsum += __shfl_down_sync(0xffffffffu, lsum, o);
        lss  += __shfl_down_sync(0xffffffffu, lss,  o);
    }
    if (lane == 0) {
        atomicAdd(&sacc[warp & 3], lsum);
        atomicAdd(&sss[warp & 3],  lss);
    }
    __syncthreads();
    if (tid < 4) {
        atomicAdd(&G_S3[b*4 + tid],  (double)sacc[tid]);
        atomicAdd(&G_SS3[b*4 + tid], (double)sss[tid]);
        __threadfence();
    }
    __syncthreads();

    if (tid == 0) {
        atomicAdd(&g_z.bar2, 1);
        while (atomicAdd(&g_z.bar2, 0) < 256) __nanosleep(128);
    }
    __syncthreads();

    if (tid < 4) {
        double s  = atomicAdd(&G_S3[b*4 + tid],  0.0);
        double ss = atomicAdd(&G_SS3[b*4 + tid], 0.0);
        double mean = s * (1.0 / 65536.0);
        double var  = ss * (1.0 / 65536.0) - mean * mean;
        sMean[tid] = (float)mean;
        sRs[tid]   = (float)rsqrt(var + 1e-5);
    }
    __syncthreads();

    {
        int gg = warp & 3;
        float ga0 = sRs[gg] * g2[cw + g];
        float bo0 = be2[cw + g] - sMean[gg] * ga0;
        float ga1 = sRs[gg] * g2[cw + g + 8];
        float bo1 = be2[cw + g + 8] - sMean[gg] * ga1;

        float2 ov;
        ov.x = fmaf(v00, ga0, bo0) + x00.x; ov.y = fmaf(v01, ga0, bo0) + x00.y;
        *(float2*)&out[r0 + col0] = ov;
        ov.x = fmaf(v02, ga1, bo1) + x01.x; ov.y = fmaf(v03, ga1, bo1) + x01.y;
        *(float2*)&out[r1 + col0] = ov;
        ov.x = fmaf(v10, ga0, bo0) + x10.x; ov.y = fmaf(v11, ga0, bo0) + x10.y;
        *(float2*)&out[r0 + col1] = ov;
        ov.x = fmaf(v12, ga1, bo1) + x11.x; ov.y = fmaf(v13, ga1, bo1) + x11.y;
        *(float2*)&out[r1 + col1] = ov;
    }
}

extern "C" void kernel_launch(void* const* d_in, const int* in_sizes, int n_in,
                              void* d_out, int out_size) {
    const float* x   = (const float*)d_in[0];
    const float* pos = (const float*)d_in[1];
    const float* w1  = (const float*)d_in[2];
    const float* b1  = (const float*)d_in[3];
    const float* g1  = (const float*)d_in[4];
    const float* be1 = (const float*)d_in[5];
    const float* wd  = (const float*)d_in[6];
    const float* gd  = (const float*)d_in[7];
    const float* bed = (const float*)d_in[8];
    const float* w2  = (const float*)d_in[9];
    const float* b2  = (const float*)d_in[10];
    const float* g2  = (const float*)d_in[11];
    const float* be2 = (const float*)d_in[12];
    float* out = (float*)d_out;

    static int inited = 0;
    if (!inited) {
        cudaFuncSetAttribute(k_prep,   cudaFuncAttributeMaxDynamicSharedMemorySize, PREP_SMEM);
        cudaFuncSetAttribute(k_gemm2f, cudaFuncAttributeMaxDynamicSharedMemorySize, G2_SMEM);
        inited = 1;
    }

    void* p_z;
    cudaGetSymbolAddress(&p_z, g_z);
    cudaMemsetAsync(p_z, 0, sizeof(ZScratch));

    k_prep  <<<384, 256, PREP_SMEM>>>(x, pos, w1, b1);
    k_gemm1f<<<dim3(NPTS/64, MM/64, BB), 256>>>(x, w1, b1, g1, be1, wd);
    k_gather<<<BB*NPTS/8, 256>>>(wd, gd, bed);
    k_gemm2f<<<256, 256, G2_SMEM>>>(w2, b2, x, g2, be2, out);
}